// round 8
// baseline (speedup 1.0000x reference)
#include <cuda_runtime.h>
#include <cuda_fp16.h>
#include <math_constants.h>

#define SEQ 4096
#define DH 64
#define NH 4
#define BM 128          // 4 warps x 32 rows
#define BN 64
#define NTILES (SEQ / BN)
#define KPAD 72
#define TSZ (BN * KPAD)
#define STAGE_B (TSZ * 2)
#define SMEM_BYTES (8 * STAGE_B)   // 4 K + 4 V stages = 73728 B

__device__ __half g_Q[4 * NH * SEQ * DH];
__device__ __half g_K[4 * NH * SEQ * DH];
__device__ __half g_V[4 * NH * SEQ * DH];

__device__ __forceinline__ unsigned pack_h2(float a, float b) {
    __half2 h = __floats2half2_rn(a, b);
    return *reinterpret_cast<unsigned*>(&h);
}
__device__ __forceinline__ unsigned ex2h2(unsigned x) {
    unsigned y; asm("ex2.approx.f16x2 %0, %1;" : "=r"(y) : "r"(x)); return y;
}
__device__ __forceinline__ unsigned expfrag(float a, float b, const __half2 cl) {
    __half2 h = __floats2half2_rn(a, b);
    h = __hmin2(h, cl);
    unsigned u = *reinterpret_cast<unsigned*>(&h);
    return ex2h2(u);
}

// ---------------- preprocess ----------------
__global__ void preprocess_kernel(
    const float* __restrict__ q_in, const float* __restrict__ k_in, const float* __restrict__ v_in,
    const float* __restrict__ wq, const float* __restrict__ bq,
    const float* __restrict__ wk, const float* __restrict__ bk,
    const float* __restrict__ wv, const float* __restrict__ bv,
    int total4)
{
    const float qs = 0.125f * 1.44269504088896340736f;
    int i4 = blockIdx.x * blockDim.x + threadIdx.x;
    if (i4 >= total4) return;
    int c4 = i4 & 63;
    int s  = (i4 >> 6) & (SEQ - 1);
    int b  = i4 >> 18;
    int c  = c4 * 4;
    int h  = c >> 6;
    int d  = c & 63;
    int in_idx  = (b * SEQ + s) * 256 + c;
    int out_idx = ((b * NH + h) * SEQ + s) * DH + d;

    float4 qv = *(const float4*)(q_in + in_idx);
    float4 kv = *(const float4*)(k_in + in_idx);
    float4 vv = *(const float4*)(v_in + in_idx);
    float4 w, bb; uint2 p;

    w = *(const float4*)(wq + c); bb = *(const float4*)(bq + c);
    p.x = pack_h2((qv.x * w.x + bb.x) * qs, (qv.y * w.y + bb.y) * qs);
    p.y = pack_h2((qv.z * w.z + bb.z) * qs, (qv.w * w.w + bb.w) * qs);
    *(uint2*)(g_Q + out_idx) = p;

    w = *(const float4*)(wk + c); bb = *(const float4*)(bk + c);
    p.x = pack_h2(kv.x * w.x + bb.x, kv.y * w.y + bb.y);
    p.y = pack_h2(kv.z * w.z + bb.z, kv.w * w.w + bb.w);
    *(uint2*)(g_K + out_idx) = p;

    w = *(const float4*)(wv + c); bb = *(const float4*)(bv + c);
    p.x = pack_h2(vv.x * w.x + bb.x, vv.y * w.y + bb.y);
    p.y = pack_h2(vv.z * w.z + bb.z, vv.w * w.w + bb.w);
    *(uint2*)(g_V + out_idx) = p;
}

// ---------------- flash attention ----------------
__device__ __forceinline__ void mma16816(float c[4], const unsigned a[4], unsigned b0, unsigned b1) {
    asm volatile(
        "mma.sync.aligned.m16n8k16.row.col.f32.f16.f16.f32 "
        "{%0,%1,%2,%3},{%4,%5,%6,%7},{%8,%9},{%0,%1,%2,%3};\n"
        : "+f"(c[0]), "+f"(c[1]), "+f"(c[2]), "+f"(c[3])
        : "r"(a[0]), "r"(a[1]), "r"(a[2]), "r"(a[3]), "r"(b0), "r"(b1));
}
__device__ __forceinline__ void ldsm_x4u(unsigned& r0, unsigned& r1, unsigned& r2, unsigned& r3, unsigned addr) {
    asm volatile("ldmatrix.sync.aligned.m8n8.x4.shared.b16 {%0,%1,%2,%3}, [%4];\n"
                 : "=r"(r0), "=r"(r1), "=r"(r2), "=r"(r3) : "r"(addr));
}
__device__ __forceinline__ void ldsm_x4tu(unsigned& r0, unsigned& r1, unsigned& r2, unsigned& r3, unsigned addr) {
    asm volatile("ldmatrix.sync.aligned.m8n8.x4.trans.shared.b16 {%0,%1,%2,%3}, [%4];\n"
                 : "=r"(r0), "=r"(r1), "=r"(r2), "=r"(r3) : "r"(addr));
}
__device__ __forceinline__ void cp16u(unsigned dst, const __half* src) {
    asm volatile("cp.async.cg.shared.global [%0], [%1], 16;\n" :: "r"(dst), "l"(src));
}

__global__ void __launch_bounds__(128, 2) attn_kernel(
    float* __restrict__ out, const float* __restrict__ wp, const float* __restrict__ bp)
{
    extern __shared__ __half smbuf[];
    __half* Ks = smbuf;
    __half* Vs = smbuf + 4 * TSZ;
    const unsigned ks_u = (unsigned)__cvta_generic_to_shared(Ks);
    const unsigned vs_u = (unsigned)__cvta_generic_to_shared(Vs);

    const int tid  = threadIdx.x;
    const int w    = tid >> 5;
    const int lane = tid & 31;
    const int gid  = lane >> 2;
    const int tig  = lane & 3;
    const __half2 cl = __floats2half2_rn(14.0f, 14.0f);

    const int bh = blockIdx.y;
    const int b  = bh >> 2;
    const int h  = bh & 3;
    const int q0 = blockIdx.x * BM;

    const __half* Qg = g_Q + bh * (SEQ * DH);
    const __half* Kg = g_K + bh * (SEQ * DH);
    const __half* Vg = g_V + bh * (SEQ * DH);

    const unsigned kbase = ks_u + ((lane & 7) * KPAD + (lane >> 3) * 8) * 2;
    const unsigned vbase = vs_u + (lane * KPAD) * 2;

    auto fillK = [&](int f) {
        if (f >= NTILES) return;
        unsigned dst0 = ks_u + (f & 3) * STAGE_B;
        const __half* src = Kg + f * BN * DH;
        #pragma unroll
        for (int i = 0; i < 4; i++) {
            int idx = i * 128 + tid;
            int r = idx >> 3, c = idx & 7;
            cp16u(dst0 + (r * KPAD + c * 8) * 2, src + r * DH + c * 8);
        }
    };
    auto fillV = [&](int f) {
        if (f >= NTILES) return;
        unsigned dst0 = vs_u + (f & 3) * STAGE_B;
        const __half* src = Vg + f * BN * DH;
        #pragma unroll
        for (int i = 0; i < 4; i++) {
            int idx = i * 128 + tid;
            int r = idx >> 3, c = idx & 7;
            cp16u(dst0 + (r * KPAD + c * 8) * 2, src + r * DH + c * 8);
        }
    };

    fillK(0); fillV(0); asm volatile("cp.async.commit_group;\n");
    fillK(1); fillV(1); asm volatile("cp.async.commit_group;\n");
    fillK(2);           asm volatile("cp.async.commit_group;\n");

    unsigned qa[2][4][4];
    #pragma unroll
    for (int m = 0; m < 2; m++) {
        const __half* qrow0 = Qg + (q0 + w * 32 + m * 16 + gid) * DH;
        const __half* qrow1 = qrow0 + 8 * DH;
        #pragma unroll
        for (int kk = 0; kk < 4; kk++) {
            int c0 = kk * 16 + tig * 2;
            qa[m][kk][0] = *(const unsigned*)(qrow0 + c0);
            qa[m][kk][1] = *(const unsigned*)(qrow1 + c0);
            qa[m][kk][2] = *(const unsigned*)(qrow0 + c0 + 8);
            qa[m][kk][3] = *(const unsigned*)(qrow1 + c0 + 8);
        }
    }

    float o[2][8][4];
    #pragma unroll
    for (int m = 0; m < 2; m++)
        #pragma unroll
        for (int j = 0; j < 8; j++)
            { o[m][j][0]=0.f; o[m][j][1]=0.f; o[m][j][2]=0.f; o[m][j][3]=0.f; }
    float mx[4];
    float l[4] = {0.f, 0.f, 0.f, 0.f};
    unsigned paA[2][4][4], paB[2][4][4];

    // QK chunk: rows j=2kk,2kk+1 of S for both m-tiles
    auto qk_chunk = [&](unsigned kst, int kk, float (&sj)[2][2][4]) {
        #pragma unroll
        for (int m = 0; m < 2; m++)
            #pragma unroll
            for (int jj = 0; jj < 2; jj++)
                { sj[m][jj][0]=0.f; sj[m][jj][1]=0.f; sj[m][jj][2]=0.f; sj[m][jj][3]=0.f; }
        #pragma unroll
        for (int jj = 0; jj < 2; jj++) {
            #pragma unroll
            for (int kk2 = 0; kk2 < 2; kk2++) {
                unsigned b0, b1, b2, b3;
                ldsm_x4u(b0, b1, b2, b3, kst + (2 * kk + jj) * (8 * KPAD * 2) + kk2 * 64);
                mma16816(sj[0][jj], qa[0][2 * kk2],     b0, b1);
                mma16816(sj[0][jj], qa[0][2 * kk2 + 1], b2, b3);
                mma16816(sj[1][jj], qa[1][2 * kk2],     b0, b1);
                mma16816(sj[1][jj], qa[1][2 * kk2 + 1], b2, b3);
            }
        }
    };
    // PV chunk: output cols jd=2kk,2kk+1 using fragments pr
    auto pv_chunk = [&](unsigned vst, int kk, const unsigned (&pr)[2][4][4]) {
        #pragma unroll
        for (int jj = 0; jj < 2; jj++) {
            int jd = 2 * kk + jj;
            #pragma unroll
            for (int kk2 = 0; kk2 < 2; kk2++) {
                unsigned b0, b1, b2, b3;
                ldsm_x4tu(b0, b1, b2, b3, vst + kk2 * (32 * KPAD * 2) + jd * 16);
                mma16816(o[0][jd], pr[0][2 * kk2],     b0, b1);
                mma16816(o[0][jd], pr[0][2 * kk2 + 1], b2, b3);
                mma16816(o[1][jd], pr[1][2 * kk2],     b0, b1);
                mma16816(o[1][jd], pr[1][2 * kk2 + 1], b2, b3);
            }
        }
    };
    // softmax chunk: sj -> pw[*][kk], accumulate l
    auto sm_chunk = [&](int kk, const float (&sj)[2][2][4], unsigned (&pw)[2][4][4]) {
        #pragma unroll
        for (int m = 0; m < 2; m++) {
            const float mn0 = mx[2 * m], mn1 = mx[2 * m + 1];
            pw[m][kk][0] = expfrag(sj[m][0][0] - mn0, sj[m][0][1] - mn0, cl);
            pw[m][kk][1] = expfrag(sj[m][0][2] - mn1, sj[m][0][3] - mn1, cl);
            pw[m][kk][2] = expfrag(sj[m][1][0] - mn0, sj[m][1][1] - mn0, cl);
            pw[m][kk][3] = expfrag(sj[m][1][2] - mn1, sj[m][1][3] - mn1, cl);
            float2 f0 = __half22float2(*reinterpret_cast<const __half2*>(&pw[m][kk][0]));
            float2 f2 = __half22float2(*reinterpret_cast<const __half2*>(&pw[m][kk][2]));
            l[2 * m] += (f0.x + f0.y) + (f2.x + f2.y);
            float2 f1 = __half22float2(*reinterpret_cast<const __half2*>(&pw[m][kk][1]));
            float2 f3 = __half22float2(*reinterpret_cast<const __half2*>(&pw[m][kk][3]));
            l[2 * m + 1] += (f1.x + f1.y) + (f3.x + f3.y);
        }
    };

    // ---- peeled tile 0: full S, freeze max, softmax -> paA, no PV ----
    {
        asm volatile("cp.async.wait_group 2;\n");
        __syncthreads();
        fillK(3); fillV(2);
        asm volatile("cp.async.commit_group;\n");
        float s[2][8][4];
        #pragma unroll
        for (int m = 0; m < 2; m++)
            #pragma unroll
            for (int j = 0; j < 8; j++)
                { s[m][j][0]=0.f; s[m][j][1]=0.f; s[m][j][2]=0.f; s[m][j][3]=0.f; }
        const unsigned kst = kbase;
        #pragma unroll
        for (int j = 0; j < 8; j++) {
            #pragma unroll
            for (int kk2 = 0; kk2 < 2; kk2++) {
                unsigned b0, b1, b2, b3;
                ldsm_x4u(b0, b1, b2, b3, kst + j * (8 * KPAD * 2) + kk2 * 64);
                mma16816(s[0][j], qa[0][2 * kk2],     b0, b1);
                mma16816(s[0][j], qa[0][2 * kk2 + 1], b2, b3);
                mma16816(s[1][j], qa[1][2 * kk2],     b0, b1);
                mma16816(s[1][j], qa[1][2 * kk2 + 1], b2, b3);
            }
        }
        #pragma unroll
        for (int m = 0; m < 2; m++) {
            float rm0 = -CUDART_INF_F, rm1 = -CUDART_INF_F;
            #pragma unroll
            for (int j = 0; j < 8; j++) {
                rm0 = fmaxf(rm0, fmaxf(s[m][j][0], s[m][j][1]));
                rm1 = fmaxf(rm1, fmaxf(s[m][j][2], s[m][j][3]));
            }
            rm0 = fmaxf(rm0, __shfl_xor_sync(0xffffffffu, rm0, 1));
            rm0 = fmaxf(rm0, __shfl_xor_sync(0xffffffffu, rm0, 2));
            rm1 = fmaxf(rm1, __shfl_xor_sync(0xffffffffu, rm1, 1));
            rm1 = fmaxf(rm1, __shfl_xor_sync(0xffffffffu, rm1, 2));
            mx[2 * m]     = rm0 + 2.0f;
            mx[2 * m + 1] = rm1 + 2.0f;
        }
        #pragma unroll
        for (int kk = 0; kk < 4; kk++) {
            float sj[2][2][4];
            #pragma unroll
            for (int m = 0; m < 2; m++)
                #pragma unroll
                for (int jj = 0; jj < 2; jj++)
                    #pragma unroll
                    for (int x = 0; x < 4; x++) sj[m][jj][x] = s[m][2 * kk + jj][x];
            sm_chunk(kk, sj, paA);
        }
    }

    // ---- main loop: tile t does QK(t)+softmax(t) interleaved with PV(t-1) ----
    auto body = [&](int t, const unsigned (&prOld)[2][4][4], unsigned (&prNew)[2][4][4]) {
        asm volatile("cp.async.wait_group 2;\n");
        __syncthreads();
        fillK(t + 3); fillV(t + 2);
        asm volatile("cp.async.commit_group;\n");
        const unsigned kst = kbase + (t & 3) * STAGE_B;
        const unsigned vst = vbase + ((t - 1) & 3) * STAGE_B;
        #pragma unroll
        for (int kk = 0; kk < 4; kk++) {
            float sj[2][2][4];
            qk_chunk(kst, kk, sj);
            sm_chunk(kk, sj, prNew);
            pv_chunk(vst, kk, prOld);   // PV(t-1): independent of this tile's softmax
        }
    };

    #pragma unroll 1
    for (int t = 1; t < NTILES - 1; t += 2) {
        body(t,     paA, paB);
        body(t + 1, paB, paA);
    }
    body(NTILES - 1, paA, paB);   // t=63: reads paA, writes paB

    // final PV(63)
    asm volatile("cp.async.wait_group 0;\n");
    __syncthreads();
    {
        const unsigned vst = vbase + ((NTILES - 1) & 3) * STAGE_B;
        #pragma unroll
        for (int kk = 0; kk < 4; kk++) pv_chunk(vst, kk, paB);
    }

    // ---- epilogue ----
    #pragma unroll
    for (int i = 0; i < 4; i++) {
        l[i] += __shfl_xor_sync(0xffffffffu, l[i], 1);
        l[i] += __shfl_xor_sync(0xffffffffu, l[i], 2);
    }
    #pragma unroll
    for (int m = 0; m < 2; m++) {
        float inv0 = 1.f / l[2 * m], inv1 = 1.f / l[2 * m + 1];
        int row0 = q0 + w * 32 + m * 16 + gid;
        float* out0 = out + (b * SEQ + row0) * 256 + h * 64;
        float* out1 = out0 + 8 * 256;
        #pragma unroll
        for (int jd = 0; jd < 8; jd++) {
            int c = jd * 8 + tig * 2;
            float2 w2 = *(const float2*)(wp + h * 64 + c);
            float2 b2 = *(const float2*)(bp + h * 64 + c);
            float2 r0, r1;
            r0.x = o[m][jd][0] * inv0 * w2.x + b2.x;
            r0.y = o[m][jd][1] * inv0 * w2.y + b2.y;
            r1.x = o[m][jd][2] * inv1 * w2.x + b2.x;
            r1.y = o[m][jd][3] * inv1 * w2.y + b2.y;
            *(float2*)(out0 + c) = r0;
            *(float2*)(out1 + c) = r1;
        }
    }
}

// ---------------- launch ----------------
extern "C" void kernel_launch(void* const* d_in, const int* in_sizes, int n_in,
                              void* d_out, int out_size)
{
    const float* q_in = (const float*)d_in[0];
    const float* k_in = (const float*)d_in[1];
    const float* v_in = (const float*)d_in[2];
    const float* wq = (const float*)d_in[3];
    const float* bq = (const float*)d_in[4];
    const float* wk = (const float*)d_in[5];
    const float* bk = (const float*)d_in[6];
    const float* wv = (const float*)d_in[7];
    const float* bv = (const float*)d_in[8];
    const float* wp = (const float*)d_in[9];
    const float* bp = (const float*)d_in[10];

    int B = in_sizes[0] / (SEQ * 256);
    int total4 = B * SEQ * 64;

    cudaFuncSetAttribute(attn_kernel, cudaFuncAttributeMaxDynamicSharedMemorySize, SMEM_BYTES);

    preprocess_kernel<<<(total4 + 255) / 256, 256>>>(
        q_in, k_in, v_in, wq, bq, wk, bk, wv, bv, total4);

    dim3 grid(SEQ / BM, B * NH);
    attn_kernel<<<grid, 128, SMEM_BYTES>>>((float*)d_out, wp, bp);
}

// round 9
// speedup vs baseline: 1.0746x; 1.0746x over previous
#include <cuda_runtime.h>
#include <cuda_fp16.h>
#include <math_constants.h>

#define SEQ 4096
#define DH 64
#define NH 4
#define BM 128          // 4 warps x 32 rows
#define BN 64
#define NTILES (SEQ / BN)
#define KPAD 72
#define TSZ (BN * KPAD)
#define STAGE_B (TSZ * 2)
#define SMEM_BYTES (8 * STAGE_B)   // 4 K + 4 V stages = 73728 B

__device__ __half g_Q[4 * NH * SEQ * DH];
__device__ __half g_K[4 * NH * SEQ * DH];
__device__ __half g_V[4 * NH * SEQ * DH];

__device__ __forceinline__ unsigned pack_h2(float a, float b) {
    __half2 h = __floats2half2_rn(a, b);
    return *reinterpret_cast<unsigned*>(&h);
}
__device__ __forceinline__ unsigned ex2h2(unsigned x) {
    unsigned y; asm("ex2.approx.f16x2 %0, %1;" : "=r"(y) : "r"(x)); return y;
}
__device__ __forceinline__ unsigned expfrag(float a, float b, const __half2 cl) {
    __half2 h = __floats2half2_rn(a, b);
    h = __hmin2(h, cl);
    unsigned u = *reinterpret_cast<unsigned*>(&h);
    return ex2h2(u);
}

// ---------------- preprocess ----------------
__global__ void preprocess_kernel(
    const float* __restrict__ q_in, const float* __restrict__ k_in, const float* __restrict__ v_in,
    const float* __restrict__ wq, const float* __restrict__ bq,
    const float* __restrict__ wk, const float* __restrict__ bk,
    const float* __restrict__ wv, const float* __restrict__ bv,
    int total4)
{
    const float qs = 0.125f * 1.44269504088896340736f;
    int i4 = blockIdx.x * blockDim.x + threadIdx.x;
    if (i4 >= total4) return;
    int c4 = i4 & 63;
    int s  = (i4 >> 6) & (SEQ - 1);
    int b  = i4 >> 18;
    int c  = c4 * 4;
    int h  = c >> 6;
    int d  = c & 63;
    int in_idx  = (b * SEQ + s) * 256 + c;
    int out_idx = ((b * NH + h) * SEQ + s) * DH + d;

    float4 qv = *(const float4*)(q_in + in_idx);
    float4 kv = *(const float4*)(k_in + in_idx);
    float4 vv = *(const float4*)(v_in + in_idx);
    float4 w, bb; uint2 p;

    w = *(const float4*)(wq + c); bb = *(const float4*)(bq + c);
    p.x = pack_h2((qv.x * w.x + bb.x) * qs, (qv.y * w.y + bb.y) * qs);
    p.y = pack_h2((qv.z * w.z + bb.z) * qs, (qv.w * w.w + bb.w) * qs);
    *(uint2*)(g_Q + out_idx) = p;

    w = *(const float4*)(wk + c); bb = *(const float4*)(bk + c);
    p.x = pack_h2(kv.x * w.x + bb.x, kv.y * w.y + bb.y);
    p.y = pack_h2(kv.z * w.z + bb.z, kv.w * w.w + bb.w);
    *(uint2*)(g_K + out_idx) = p;

    w = *(const float4*)(wv + c); bb = *(const float4*)(bv + c);
    p.x = pack_h2(vv.x * w.x + bb.x, vv.y * w.y + bb.y);
    p.y = pack_h2(vv.z * w.z + bb.z, vv.w * w.w + bb.w);
    *(uint2*)(g_V + out_idx) = p;
}

// ---------------- flash attention ----------------
__device__ __forceinline__ void mma16816(float c[4], const unsigned a[4], unsigned b0, unsigned b1) {
    asm volatile(
        "mma.sync.aligned.m16n8k16.row.col.f32.f16.f16.f32 "
        "{%0,%1,%2,%3},{%4,%5,%6,%7},{%8,%9},{%0,%1,%2,%3};\n"
        : "+f"(c[0]), "+f"(c[1]), "+f"(c[2]), "+f"(c[3])
        : "r"(a[0]), "r"(a[1]), "r"(a[2]), "r"(a[3]), "r"(b0), "r"(b1));
}
__device__ __forceinline__ void ldsm_x4u(unsigned& r0, unsigned& r1, unsigned& r2, unsigned& r3, unsigned addr) {
    asm volatile("ldmatrix.sync.aligned.m8n8.x4.shared.b16 {%0,%1,%2,%3}, [%4];\n"
                 : "=r"(r0), "=r"(r1), "=r"(r2), "=r"(r3) : "r"(addr));
}
__device__ __forceinline__ void ldsm_x4tu(unsigned& r0, unsigned& r1, unsigned& r2, unsigned& r3, unsigned addr) {
    asm volatile("ldmatrix.sync.aligned.m8n8.x4.trans.shared.b16 {%0,%1,%2,%3}, [%4];\n"
                 : "=r"(r0), "=r"(r1), "=r"(r2), "=r"(r3) : "r"(addr));
}
__device__ __forceinline__ void cp16u(unsigned dst, const __half* src) {
    asm volatile("cp.async.cg.shared.global [%0], [%1], 16;\n" :: "r"(dst), "l"(src));
}

__global__ void __launch_bounds__(128, 2) attn_kernel(
    float* __restrict__ out, const float* __restrict__ wp, const float* __restrict__ bp)
{
    extern __shared__ __half smbuf[];
    __half* Ks = smbuf;
    __half* Vs = smbuf + 4 * TSZ;
    const unsigned ks_u = (unsigned)__cvta_generic_to_shared(Ks);
    const unsigned vs_u = (unsigned)__cvta_generic_to_shared(Vs);

    const int tid  = threadIdx.x;
    const int w    = tid >> 5;
    const int lane = tid & 31;
    const int gid  = lane >> 2;
    const int tig  = lane & 3;
    const __half2 cl = __floats2half2_rn(14.0f, 14.0f);

    const int bh = blockIdx.y;
    const int b  = bh >> 2;
    const int h  = bh & 3;
    const int q0 = blockIdx.x * BM;

    const __half* Qg = g_Q + bh * (SEQ * DH);
    const __half* Kg = g_K + bh * (SEQ * DH);
    const __half* Vg = g_V + bh * (SEQ * DH);

    const unsigned kbase = ks_u + ((lane & 7) * KPAD + (lane >> 3) * 8) * 2;
    const unsigned vbase = vs_u + (lane * KPAD) * 2;

    auto fillK = [&](int f) {
        if (f >= NTILES) return;
        unsigned dst0 = ks_u + (f & 3) * STAGE_B;
        const __half* src = Kg + f * BN * DH;
        #pragma unroll
        for (int i = 0; i < 4; i++) {
            int idx = i * 128 + tid;
            int r = idx >> 3, c = idx & 7;
            cp16u(dst0 + (r * KPAD + c * 8) * 2, src + r * DH + c * 8);
        }
    };
    auto fillV = [&](int f) {
        if (f >= NTILES) return;
        unsigned dst0 = vs_u + (f & 3) * STAGE_B;
        const __half* src = Vg + f * BN * DH;
        #pragma unroll
        for (int i = 0; i < 4; i++) {
            int idx = i * 128 + tid;
            int r = idx >> 3, c = idx & 7;
            cp16u(dst0 + (r * KPAD + c * 8) * 2, src + r * DH + c * 8);
        }
    };

    fillK(0); fillV(0); asm volatile("cp.async.commit_group;\n");
    fillK(1); fillV(1); asm volatile("cp.async.commit_group;\n");
    fillK(2);           asm volatile("cp.async.commit_group;\n");

    unsigned qa[2][4][4];
    #pragma unroll
    for (int m = 0; m < 2; m++) {
        const __half* qrow0 = Qg + (q0 + w * 32 + m * 16 + gid) * DH;
        const __half* qrow1 = qrow0 + 8 * DH;
        #pragma unroll
        for (int kk = 0; kk < 4; kk++) {
            int c0 = kk * 16 + tig * 2;
            qa[m][kk][0] = *(const unsigned*)(qrow0 + c0);
            qa[m][kk][1] = *(const unsigned*)(qrow1 + c0);
            qa[m][kk][2] = *(const unsigned*)(qrow0 + c0 + 8);
            qa[m][kk][3] = *(const unsigned*)(qrow1 + c0 + 8);
        }
    }

    float o[2][8][4];
    #pragma unroll
    for (int m = 0; m < 2; m++)
        #pragma unroll
        for (int j = 0; j < 8; j++)
            { o[m][j][0]=0.f; o[m][j][1]=0.f; o[m][j][2]=0.f; o[m][j][3]=0.f; }
    float mx[4];
    float l[4] = {0.f, 0.f, 0.f, 0.f};

    // ---- QK half: computes S rows j = 4*half .. 4*half+3 for both m-tiles ----
    auto qk_half = [&](unsigned kst, int half, float (&sj)[2][4][4]) {
        #pragma unroll
        for (int m = 0; m < 2; m++)
            #pragma unroll
            for (int jj = 0; jj < 4; jj++)
                { sj[m][jj][0]=0.f; sj[m][jj][1]=0.f; sj[m][jj][2]=0.f; sj[m][jj][3]=0.f; }
        #pragma unroll
        for (int jj = 0; jj < 4; jj++) {
            int j = 4 * half + jj;
            #pragma unroll
            for (int kd = 0; kd < 2; kd++) {
                unsigned b0, b1, b2, b3;
                ldsm_x4u(b0, b1, b2, b3, kst + j * (8 * KPAD * 2) + kd * 64);
                mma16816(sj[0][jj], qa[0][2 * kd],     b0, b1);
                mma16816(sj[0][jj], qa[0][2 * kd + 1], b2, b3);
                mma16816(sj[1][jj], qa[1][2 * kd],     b0, b1);
                mma16816(sj[1][jj], qa[1][2 * kd + 1], b2, b3);
            }
        }
    };
    // ---- softmax half: sj (4 j-rows) -> pa k-slices 2*half, 2*half+1 ----
    auto sm_half = [&](int half, const float (&sj)[2][4][4], unsigned (&pa)[2][4][4]) {
        #pragma unroll
        for (int c = 0; c < 2; c++) {
            int kk = 2 * half + c;
            #pragma unroll
            for (int m = 0; m < 2; m++) {
                const float mn0 = mx[2 * m], mn1 = mx[2 * m + 1];
                pa[m][kk][0] = expfrag(sj[m][2 * c][0] - mn0,     sj[m][2 * c][1] - mn0,     cl);
                pa[m][kk][1] = expfrag(sj[m][2 * c][2] - mn1,     sj[m][2 * c][3] - mn1,     cl);
                pa[m][kk][2] = expfrag(sj[m][2 * c + 1][0] - mn0, sj[m][2 * c + 1][1] - mn0, cl);
                pa[m][kk][3] = expfrag(sj[m][2 * c + 1][2] - mn1, sj[m][2 * c + 1][3] - mn1, cl);
                float2 f0 = __half22float2(*reinterpret_cast<const __half2*>(&pa[m][kk][0]));
                float2 f2 = __half22float2(*reinterpret_cast<const __half2*>(&pa[m][kk][2]));
                l[2 * m] += (f0.x + f0.y) + (f2.x + f2.y);
                float2 f1 = __half22float2(*reinterpret_cast<const __half2*>(&pa[m][kk][1]));
                float2 f3 = __half22float2(*reinterpret_cast<const __half2*>(&pa[m][kk][3]));
                l[2 * m + 1] += (f1.x + f1.y) + (f3.x + f3.y);
            }
        }
    };
    // ---- PV half: O += P[:, keys 32*half..+32) @ V[same keys, :] over all 8 jd ----
    auto pv_half = [&](unsigned vst, int half, const unsigned (&pa)[2][4][4]) {
        #pragma unroll
        for (int jd = 0; jd < 8; jd++) {
            unsigned b0, b1, b2, b3;
            ldsm_x4tu(b0, b1, b2, b3, vst + half * (32 * KPAD * 2) + jd * 16);
            mma16816(o[0][jd], pa[0][2 * half],     b0, b1);
            mma16816(o[0][jd], pa[0][2 * half + 1], b2, b3);
            mma16816(o[1][jd], pa[1][2 * half],     b0, b1);
            mma16816(o[1][jd], pa[1][2 * half + 1], b2, b3);
        }
    };

    #pragma unroll 1
    for (int t = 0; t < NTILES; t++) {
        if (t + 1 < NTILES) asm volatile("cp.async.wait_group 2;\n");
        else                asm volatile("cp.async.wait_group 0;\n");
        __syncthreads();
        fillK(t + 3);
        fillV(t + 2);
        asm volatile("cp.async.commit_group;\n");

        const unsigned kst = kbase + (t & 3) * STAGE_B;
        const unsigned vst = vbase + (t & 3) * STAGE_B;
        unsigned pa[2][4][4];

        if (t == 0) {
            // full S needed to freeze row max
            float s0[2][4][4], s1[2][4][4];
            qk_half(kst, 0, s0);
            qk_half(kst, 1, s1);
            #pragma unroll
            for (int m = 0; m < 2; m++) {
                float rm0 = -CUDART_INF_F, rm1 = -CUDART_INF_F;
                #pragma unroll
                for (int jj = 0; jj < 4; jj++) {
                    rm0 = fmaxf(rm0, fmaxf(fmaxf(s0[m][jj][0], s0[m][jj][1]), fmaxf(s1[m][jj][0], s1[m][jj][1])));
                    rm1 = fmaxf(rm1, fmaxf(fmaxf(s0[m][jj][2], s0[m][jj][3]), fmaxf(s1[m][jj][2], s1[m][jj][3])));
                }
                rm0 = fmaxf(rm0, __shfl_xor_sync(0xffffffffu, rm0, 1));
                rm0 = fmaxf(rm0, __shfl_xor_sync(0xffffffffu, rm0, 2));
                rm1 = fmaxf(rm1, __shfl_xor_sync(0xffffffffu, rm1, 1));
                rm1 = fmaxf(rm1, __shfl_xor_sync(0xffffffffu, rm1, 2));
                mx[2 * m]     = rm0 + 2.0f;
                mx[2 * m + 1] = rm1 + 2.0f;
            }
            sm_half(0, s0, pa);
            sm_half(1, s1, pa);
            pv_half(vst, 0, pa);
            pv_half(vst, 1, pa);
        } else {
            // interleaved: QK0, SM0, QK1, PV0, SM1, PV1
            float s0[2][4][4];
            qk_half(kst, 0, s0);
            sm_half(0, s0, pa);
            float s1[2][4][4];
            qk_half(kst, 1, s1);     // HMMAs overlap SM0's MUFU tail
            pv_half(vst, 0, pa);     // HMMAs overlap SM1 below via scoreboard
            sm_half(1, s1, pa);
            pv_half(vst, 1, pa);
        }
    }

    // ---- epilogue ----
    #pragma unroll
    for (int i = 0; i < 4; i++) {
        l[i] += __shfl_xor_sync(0xffffffffu, l[i], 1);
        l[i] += __shfl_xor_sync(0xffffffffu, l[i], 2);
    }
    #pragma unroll
    for (int m = 0; m < 2; m++) {
        float inv0 = 1.f / l[2 * m], inv1 = 1.f / l[2 * m + 1];
        int row0 = q0 + w * 32 + m * 16 + gid;
        float* out0 = out + (b * SEQ + row0) * 256 + h * 64;
        float* out1 = out0 + 8 * 256;
        #pragma unroll
        for (int jd = 0; jd < 8; jd++) {
            int c = jd * 8 + tig * 2;
            float2 w2 = *(const float2*)(wp + h * 64 + c);
            float2 b2 = *(const float2*)(bp + h * 64 + c);
            float2 r0, r1;
            r0.x = o[m][jd][0] * inv0 * w2.x + b2.x;
            r0.y = o[m][jd][1] * inv0 * w2.y + b2.y;
            r1.x = o[m][jd][2] * inv1 * w2.x + b2.x;
            r1.y = o[m][jd][3] * inv1 * w2.y + b2.y;
            *(float2*)(out0 + c) = r0;
            *(float2*)(out1 + c) = r1;
        }
    }
}

// ---------------- launch ----------------
extern "C" void kernel_launch(void* const* d_in, const int* in_sizes, int n_in,
                              void* d_out, int out_size)
{
    const float* q_in = (const float*)d_in[0];
    const float* k_in = (const float*)d_in[1];
    const float* v_in = (const float*)d_in[2];
    const float* wq = (const float*)d_in[3];
    const float* bq = (const float*)d_in[4];
    const float* wk = (const float*)d_in[5];
    const float* bk = (const float*)d_in[6];
    const float* wv = (const float*)d_in[7];
    const float* bv = (const float*)d_in[8];
    const float* wp = (const float*)d_in[9];
    const float* bp = (const float*)d_in[10];

    int B = in_sizes[0] / (SEQ * 256);
    int total4 = B * SEQ * 64;

    cudaFuncSetAttribute(attn_kernel, cudaFuncAttributeMaxDynamicSharedMemorySize, SMEM_BYTES);

    preprocess_kernel<<<(total4 + 255) / 256, 256>>>(
        q_in, k_in, v_in, wq, bq, wk, bk, wv, bv, total4);

    dim3 grid(SEQ / BM, B * NH);
    attn_kernel<<<grid, 128, SMEM_BYTES>>>((float*)d_out, wp, bp);
}